// round 14
// baseline (speedup 1.0000x reference)
#include <cuda_runtime.h>
#include <cuda_bf16.h>
#include <cstdint>

#define WDIM 1024
#define NPIX (WDIM * WDIM)
#define TPC 4
#define NCTA (NPIX / 128 / TPC)   // 2048

static __device__ __forceinline__ float bt(float v) {
    return __bfloat162float(__float2bfloat16_rn(v));
}
static __device__ __forceinline__ uint32_t pk(float lo, float hi) {
    uint32_t r;
    asm("cvt.rn.bf16x2.f32 %0, %1, %2;" : "=r"(r) : "f"(hi), "f"(lo));
    return r;
}
static __device__ __forceinline__ uint32_t smem_u32(const void* p) {
    uint32_t a;
    asm("{ .reg .u64 t; cvta.to.shared.u64 t, %1; cvt.u32.u64 %0, t; }" : "=r"(a) : "l"(p));
    return a;
}
static __device__ __forceinline__ void mma16816(float* d, const uint32_t* a,
                                                uint32_t b0, uint32_t b1) {
    asm volatile(
        "mma.sync.aligned.m16n8k16.row.col.f32.bf16.bf16.f32 "
        "{%0,%1,%2,%3}, {%4,%5,%6,%7}, {%8,%9}, {%0,%1,%2,%3};"
        : "+f"(d[0]), "+f"(d[1]), "+f"(d[2]), "+f"(d[3])
        : "r"(a[0]), "r"(a[1]), "r"(a[2]), "r"(a[3]), "r"(b0), "r"(b1));
}
static __device__ __forceinline__ void ldm4(uint32_t* r, uint32_t addr) {
    asm volatile("ldmatrix.sync.aligned.m8n8.x4.shared.b16 {%0,%1,%2,%3}, [%4];"
                 : "=r"(r[0]), "=r"(r[1]), "=r"(r[2]), "=r"(r[3]) : "r"(addr));
}

// softmax(9) + inverse rotation (register selects) + tanh + sigmoid; coalesced stores.
static __device__ __forceinline__ void epilogue(const float* z, int d, int p,
                                                float* __restrict__ out)
{
    const int rb0 = d & 1;
    const int rb1 = (d >> 1) & 1;

    float mx = z[0];
#pragma unroll
    for (int j = 1; j < 9; j++) mx = fmaxf(mx, z[j]);
    float s[9];
    float sum = 0.0f;
#pragma unroll
    for (int j = 0; j < 9; j++) { s[j] = __expf(z[j] - mx); sum += s[j]; }
    float inv = __fdividef(1.0f, sum);

    const int I0[9] = {0,1,2,3,4,5,6,7,8};
    const int I1[9] = {2,5,8,1,4,7,0,3,6};
    const int I2[9] = {8,7,6,5,4,3,2,1,0};
    const int I3[9] = {6,3,0,7,4,1,8,5,2};
#pragma unroll
    for (int m = 0; m < 9; m++) {
        float v01 = rb0 ? s[I1[m]] : s[I0[m]];
        float v23 = rb0 ? s[I3[m]] : s[I2[m]];
        float v = rb1 ? v23 : v01;
        out[m * NPIX + p] = v * inv;
    }
    out[9 * NPIX + p] = tanhf(z[9]);
#pragma unroll
    for (int m = 0; m < 3; m++)
        out[(10 + m) * NPIX + p] = __fdividef(1.0f, 1.0f + __expf(-z[10 + m]));
}

__global__ void __launch_bounds__(128, 3) energy_cnn_hmma_kernel(
    const float* __restrict__ se, const float* __restrict__ te,
    const float* __restrict__ sr, const float* __restrict__ hc,
    const float* __restrict__ rot, const float* __restrict__ w1,
    const float* __restrict__ b1, const float* __restrict__ w2,
    const float* __restrict__ b2, float* __restrict__ out)
{
    // A tiles: 128 rows x 64 bf16 (128B rows), XOR-16B-chunk swizzle.
    __shared__ __align__(128) uint8_t Ahi[128 * 128];
    __shared__ __align__(128) uint8_t Alo[128 * 128];
    // z staging, pitch 17 floats (conflict-free column reads).
    __shared__ float ZS[128 * 17];

    const int tid = threadIdx.x;
    const int lane = tid & 31, wid = tid >> 5;
    const int q = lane & 3, nrow = lane >> 2;

    // ---- ALL B fragments in registers (per warp, computed once) ----
    uint32_t w1h[4][4][2];     // 32 regs
    uint2    w1lo[16];         // 32 regs
    uint2    w2hr[4], w2lr[4]; // 16 regs
#pragma unroll
    for (int kt = 0; kt < 4; kt++)
#pragma unroll
    for (int nt = 0; nt < 4; nt++) {
        const int n = nt * 8 + nrow;
        const int k0 = kt * 16 + q * 2;
        float v[4];
#pragma unroll
        for (int u = 0; u < 4; u++) {
            int k = k0 + (u >> 1) * 8 + (u & 1);
            v[u] = (k < 54) ? __ldg(&w1[n * 54 + k]) : ((k == 54) ? __ldg(&b1[n]) : 0.0f);
        }
        float h0 = bt(v[0]), h1 = bt(v[1]), h2 = bt(v[2]), h3 = bt(v[3]);
        w1h[kt][nt][0] = pk(h0, h1);
        w1h[kt][nt][1] = pk(h2, h3);
        w1lo[kt * 4 + nt] =
            make_uint2(pk(v[0] - h0, v[1] - h1), pk(v[2] - h2, v[3] - h3));
    }
#pragma unroll
    for (int kt = 0; kt < 2; kt++)
#pragma unroll
    for (int nt = 0; nt < 2; nt++) {
        const int n = nt * 8 + nrow;
        const int k0 = kt * 16 + q * 2;
        float v[4];
#pragma unroll
        for (int u = 0; u < 4; u++) {
            int k = k0 + (u >> 1) * 8 + (u & 1);
            v[u] = (n < 13) ? __ldg(&w2[n * 32 + k]) : 0.0f;
        }
        float h0 = bt(v[0]), h1 = bt(v[1]), h2 = bt(v[2]), h3 = bt(v[3]);
        w2hr[kt * 2 + nt] = make_uint2(pk(h0, h1), pk(h2, h3));
        w2lr[kt * 2 + nt] =
            make_uint2(pk(v[0] - h0, v[1] - h1), pk(v[2] - h2, v[3] - h3));
    }
    float b2r[13];
#pragma unroll
    for (int m = 0; m < 13; m++) b2r[m] = __ldg(&b2[m]);

    const uint32_t sAhi = smem_u32(Ahi), sAlo = smem_u32(Alo);
    const float* chans[6] = { se, te, sr, hc, hc + NPIX, hc + 2 * NPIX };
    const float TP = 6.2831853071795864f;

    // Constant zero chunk 7 of each A-tile row: write ONCE (never overwritten).
    const int rx = tid & 7;
    const uint32_t rowo = (uint32_t)tid * 128u;
    {
        const uint32_t off7 = rowo + ((uint32_t)(7 ^ rx) << 4);
        *(uint4*)(Ahi + off7) = make_uint4(0u, 0u, 0u, 0u);
        *(uint4*)(Alo + off7) = make_uint4(0u, 0u, 0u, 0u);
    }

    for (int t = 0; t < TPC; t++) {
        const int p = (blockIdx.x * TPC + t) * 128 + tid;
        const int x = p & (WDIM - 1);
        const int y = p >> 10;

        float tt = __ldg(&rot[p]) / TP * 4.0f;
        const int dd = ((int)tt) & 3;
        const int rb0 = dd & 1, rb1 = (dd >> 1) & 1;

        // UNROTATED gather addresses (coalesced), rotate in registers.
        int idx[9];
#pragma unroll
        for (int j = 0; j < 9; j++) {
            const int dy0 = j / 3 - 1, dx0 = j % 3 - 1;
            idx[j] = (((y + dy0) & (WDIM - 1)) << 10) + ((x + dx0) & (WDIM - 1));
        }

        const int T1[9] = {6,3,0,7,4,1,8,5,2};
        const int T3[9] = {2,5,8,1,4,7,0,3,6};

        // Streamed hi/lo pack into swizzled A-tile rows (no a[54] buffer).
        float ph = 0.0f, pl = 0.0f;
        uint32_t chh[4], cll[4];
#pragma unroll
        for (int c = 0; c < 6; c++) {
            const float* __restrict__ chp = chans[c];
            float pr[9];
#pragma unroll
            for (int j = 0; j < 9; j++) pr[j] = __ldg(&chp[idx[j]]);
#pragma unroll
            for (int j = 0; j < 9; j++) {
                float v01 = rb0 ? pr[T1[j]] : pr[j];
                float v23 = rb0 ? pr[T3[j]] : pr[8 - j];
                float v = rb1 ? v23 : v01;
                const int k = c * 9 + j;            // compile-time K position
                float hv = bt(v);
                float lv = v - hv;
                if ((k & 1) == 0) { ph = hv; pl = lv; }
                else {
                    const int w = (k & 7) >> 1;
                    chh[w] = pk(ph, hv);
                    cll[w] = pk(pl, lv);
                    if ((k & 7) == 7) {
                        const uint32_t off = rowo + ((uint32_t)((k >> 3) ^ rx) << 4);
                        *(uint4*)(Ahi + off) = make_uint4(chh[0], chh[1], chh[2], chh[3]);
                        *(uint4*)(Alo + off) = make_uint4(cll[0], cll[1], cll[2], cll[3]);
                    }
                }
            }
        }
        {   // finish chunk 6: K=54 bias (=1 exact), K=55 pad
            chh[3] = pk(1.0f, 0.0f);
            cll[3] = 0u;
            const uint32_t off6 = rowo + ((uint32_t)(6 ^ rx) << 4);
            *(uint4*)(Ahi + off6) = make_uint4(chh[0], chh[1], chh[2], chh[3]);
            *(uint4*)(Alo + off6) = make_uint4(cll[0], cll[1], cll[2], cll[3]);
        }
        __syncwarp();

        // ---- per-warp MMA over its 32 rows (two 16-row subtiles) ----
#pragma unroll
        for (int smt = 0; smt < 2; smt++) {
            const int rl = wid * 32 + smt * 16 + (lane & 15);
            const uint32_t rbase = (uint32_t)rl * 128u;
            const int rrx = rl & 7;
            const int sel = lane >> 4;

            uint32_t af[4][4];
#pragma unroll
            for (int kt = 0; kt < 4; kt++)
                ldm4(af[kt], sAhi + rbase + ((uint32_t)((kt * 2 + sel) ^ rrx) << 4));

            float d1[4][4];
#pragma unroll
            for (int nt = 0; nt < 4; nt++)
#pragma unroll
                for (int u = 0; u < 4; u++) d1[nt][u] = 0.0f;

#pragma unroll
            for (int nt = 0; nt < 4; nt++)
#pragma unroll
            for (int kt = 0; kt < 4; kt++) {
                mma16816(d1[nt], af[kt], w1h[kt][nt][0], w1h[kt][nt][1]);   // Ah*Wh
                mma16816(d1[nt], af[kt], w1lo[kt * 4 + nt].x, w1lo[kt * 4 + nt].y); // Ah*Wl
            }
#pragma unroll
            for (int kt = 0; kt < 4; kt++)
                ldm4(af[kt], sAlo + rbase + ((uint32_t)((kt * 2 + sel) ^ rrx) << 4));
#pragma unroll
            for (int nt = 0; nt < 4; nt++)
#pragma unroll
            for (int kt = 0; kt < 4; kt++)
                mma16816(d1[nt], af[kt], w1h[kt][nt][0], w1h[kt][nt][1]);   // Al*Wh

            // ---- ReLU + hi/lo split -> layer-2 A fragments, register-resident ----
            uint32_t a2h[2][4], a2l[2][4];
#pragma unroll
            for (int kt2 = 0; kt2 < 2; kt2++) {
#pragma unroll
                for (int hh = 0; hh < 2; hh++) {     // D1 n-tile = 2*kt2 + hh
                    float* e = d1[2 * kt2 + hh];
                    float r0 = fmaxf(e[0], 0.0f), r1 = fmaxf(e[1], 0.0f);
                    float r2 = fmaxf(e[2], 0.0f), r3 = fmaxf(e[3], 0.0f);
                    float t0 = bt(r0), t1 = bt(r1), t2 = bt(r2), t3 = bt(r3);
                    a2h[kt2][hh * 2 + 0] = pk(t0, t1);
                    a2h[kt2][hh * 2 + 1] = pk(t2, t3);
                    a2l[kt2][hh * 2 + 0] = pk(r0 - t0, r1 - t1);
                    a2l[kt2][hh * 2 + 1] = pk(r2 - t2, r3 - t3);
                }
            }

            float d2[2][4];
#pragma unroll
            for (int nt2 = 0; nt2 < 2; nt2++)
#pragma unroll
                for (int u = 0; u < 4; u++) d2[nt2][u] = 0.0f;

#pragma unroll
            for (int nt2 = 0; nt2 < 2; nt2++)
#pragma unroll
            for (int kt2 = 0; kt2 < 2; kt2++) {
                uint2 bh = w2hr[kt2 * 2 + nt2];
                uint2 bl = w2lr[kt2 * 2 + nt2];
                mma16816(d2[nt2], a2h[kt2], bh.x, bh.y);
                mma16816(d2[nt2], a2h[kt2], bl.x, bl.y);
                mma16816(d2[nt2], a2l[kt2], bh.x, bh.y);
            }

            const int r0w = wid * 32 + smt * 16 + nrow;
#pragma unroll
            for (int nt2 = 0; nt2 < 2; nt2++) {
                const int col = nt2 * 8 + q * 2;
                ZS[r0w * 17 + col]           = d2[nt2][0];
                ZS[r0w * 17 + col + 1]       = d2[nt2][1];
                ZS[(r0w + 8) * 17 + col]     = d2[nt2][2];
                ZS[(r0w + 8) * 17 + col + 1] = d2[nt2][3];
            }
        }
        __syncwarp();

        float z[13];
#pragma unroll
        for (int m = 0; m < 13; m++) z[m] = ZS[tid * 17 + m] + b2r[m];
        epilogue(z, dd, p, out);
        __syncwarp();
    }
}

extern "C" void kernel_launch(void* const* d_in, const int* in_sizes, int n_in,
                              void* d_out, int out_size)
{
    const float* se  = (const float*)d_in[0];
    const float* te  = (const float*)d_in[1];
    const float* sr  = (const float*)d_in[2];
    const float* hc  = (const float*)d_in[3];
    const float* rot = (const float*)d_in[4];
    const float* w1  = (const float*)d_in[5];
    const float* b1  = (const float*)d_in[6];
    const float* w2  = (const float*)d_in[7];
    const float* b2  = (const float*)d_in[8];
    float* out = (float*)d_out;

    energy_cnn_hmma_kernel<<<NCTA, 128>>>(se, te, sr, hc, rot, w1, b1, w2, b2, out);
}

// round 15
// speedup vs baseline: 1.0486x; 1.0486x over previous
#include <cuda_runtime.h>
#include <cuda_bf16.h>
#include <cstdint>

#define WDIM 1024
#define NPIX (WDIM * WDIM)
#define TPC 4
#define NCTA (NPIX / 128 / TPC)   // 2048

static __device__ __forceinline__ float bt(float v) {
    return __bfloat162float(__float2bfloat16_rn(v));
}
static __device__ __forceinline__ uint32_t pk(float lo, float hi) {
    uint32_t r;
    asm("cvt.rn.bf16x2.f32 %0, %1, %2;" : "=r"(r) : "f"(hi), "f"(lo));
    return r;
}
static __device__ __forceinline__ uint32_t smem_u32(const void* p) {
    uint32_t a;
    asm("{ .reg .u64 t; cvta.to.shared.u64 t, %1; cvt.u32.u64 %0, t; }" : "=r"(a) : "l"(p));
    return a;
}
static __device__ __forceinline__ void mma16816(float* d, const uint32_t* a,
                                                uint32_t b0, uint32_t b1) {
    asm volatile(
        "mma.sync.aligned.m16n8k16.row.col.f32.bf16.bf16.f32 "
        "{%0,%1,%2,%3}, {%4,%5,%6,%7}, {%8,%9}, {%0,%1,%2,%3};"
        : "+f"(d[0]), "+f"(d[1]), "+f"(d[2]), "+f"(d[3])
        : "r"(a[0]), "r"(a[1]), "r"(a[2]), "r"(a[3]), "r"(b0), "r"(b1));
}
static __device__ __forceinline__ void mma16808(float* d, uint32_t a0, uint32_t a1,
                                                uint32_t b0) {
    asm volatile(
        "mma.sync.aligned.m16n8k8.row.col.f32.bf16.bf16.f32 "
        "{%0,%1,%2,%3}, {%4,%5}, {%6}, {%0,%1,%2,%3};"
        : "+f"(d[0]), "+f"(d[1]), "+f"(d[2]), "+f"(d[3])
        : "r"(a0), "r"(a1), "r"(b0));
}
static __device__ __forceinline__ void ldm4(uint32_t* r, uint32_t addr) {
    asm volatile("ldmatrix.sync.aligned.m8n8.x4.shared.b16 {%0,%1,%2,%3}, [%4];"
                 : "=r"(r[0]), "=r"(r[1]), "=r"(r[2]), "=r"(r[3]) : "r"(addr));
}

// softmax(9) + inverse rotation (register selects) + tanh + sigmoid; coalesced stores.
static __device__ __forceinline__ void epilogue(const float* z, int d, int p,
                                                float* __restrict__ out)
{
    const int rb0 = d & 1;
    const int rb1 = (d >> 1) & 1;

    float mx = z[0];
#pragma unroll
    for (int j = 1; j < 9; j++) mx = fmaxf(mx, z[j]);
    float s[9];
    float sum = 0.0f;
#pragma unroll
    for (int j = 0; j < 9; j++) { s[j] = __expf(z[j] - mx); sum += s[j]; }
    float inv = __fdividef(1.0f, sum);

    const int I0[9] = {0,1,2,3,4,5,6,7,8};
    const int I1[9] = {2,5,8,1,4,7,0,3,6};
    const int I2[9] = {8,7,6,5,4,3,2,1,0};
    const int I3[9] = {6,3,0,7,4,1,8,5,2};
#pragma unroll
    for (int m = 0; m < 9; m++) {
        float v01 = rb0 ? s[I1[m]] : s[I0[m]];
        float v23 = rb0 ? s[I3[m]] : s[I2[m]];
        float v = rb1 ? v23 : v01;
        out[m * NPIX + p] = v * inv;
    }
    out[9 * NPIX + p] = tanhf(z[9]);
#pragma unroll
    for (int m = 0; m < 3; m++)
        out[(10 + m) * NPIX + p] = __fdividef(1.0f, 1.0f + __expf(-z[10 + m]));
}

__global__ void __launch_bounds__(128, 4) energy_cnn_hmma_kernel(
    const float* __restrict__ se, const float* __restrict__ te,
    const float* __restrict__ sr, const float* __restrict__ hc,
    const float* __restrict__ rot, const float* __restrict__ w1,
    const float* __restrict__ b1, const float* __restrict__ w2,
    const float* __restrict__ b2, float* __restrict__ out)
{
    // A tiles: 128 rows x 64 bf16 (128B rows), XOR-16B-chunk swizzle.
    __shared__ __align__(128) uint8_t Ahi[128 * 128];
    __shared__ __align__(128) uint8_t Alo[128 * 128];
    // w2 fragment bank [frag][lane] (kept in smem: only 32 wf/warp-tile).
    __shared__ __align__(16) uint2 W2H[4 * 32];
    __shared__ __align__(16) uint2 W2L[4 * 32];
    __shared__ float B2S[13];
    // z staging, pitch 17 floats (conflict-free column reads).
    __shared__ float ZS[128 * 17];

    const int tid = threadIdx.x;
    const int lane = tid & 31, wid = tid >> 5;
    const int q = lane & 3, nrow = lane >> 2;

    // ---- w1 fragments in REGISTERS (per warp); kt=3 uses k8 form (K56-63 == 0) ----
    uint32_t w1h[4][4][2];   // [3][nt][1] dead (zeros) -> eliminated
    uint2    w1lo[16];       // [12..15].y dead -> eliminated
#pragma unroll
    for (int kt = 0; kt < 4; kt++)
#pragma unroll
    for (int nt = 0; nt < 4; nt++) {
        const int n = nt * 8 + nrow;
        const int k0 = kt * 16 + q * 2;
        float v[4];
#pragma unroll
        for (int u = 0; u < 4; u++) {
            int k = k0 + (u >> 1) * 8 + (u & 1);
            v[u] = (k < 54) ? __ldg(&w1[n * 54 + k]) : ((k == 54) ? __ldg(&b1[n]) : 0.0f);
        }
        float h0 = bt(v[0]), h1 = bt(v[1]), h2 = bt(v[2]), h3 = bt(v[3]);
        w1h[kt][nt][0] = pk(h0, h1);
        w1h[kt][nt][1] = pk(h2, h3);
        w1lo[kt * 4 + nt] =
            make_uint2(pk(v[0] - h0, v[1] - h1), pk(v[2] - h2, v[3] - h3));
    }
    // w2 bank (built by warp 0; values lane-indexed, same for all warps)
    if (wid == 0) {
#pragma unroll
        for (int kt = 0; kt < 2; kt++)
#pragma unroll
        for (int nt = 0; nt < 2; nt++) {
            const int n = nt * 8 + nrow;
            const int k0 = kt * 16 + q * 2;
            float v[4];
#pragma unroll
            for (int u = 0; u < 4; u++) {
                int k = k0 + (u >> 1) * 8 + (u & 1);
                v[u] = (n < 13) ? __ldg(&w2[n * 32 + k]) : 0.0f;
            }
            float h0 = bt(v[0]), h1 = bt(v[1]), h2 = bt(v[2]), h3 = bt(v[3]);
            W2H[(kt * 2 + nt) * 32 + lane] = make_uint2(pk(h0, h1), pk(h2, h3));
            W2L[(kt * 2 + nt) * 32 + lane] =
                make_uint2(pk(v[0] - h0, v[1] - h1), pk(v[2] - h2, v[3] - h3));
        }
    }
    if (tid < 13) B2S[tid] = b2[tid];
    __syncthreads();

    const uint32_t sAhi = smem_u32(Ahi), sAlo = smem_u32(Alo);
    const float TP = 6.2831853071795864f;

    // Constant zero chunk 7 of each A-tile row: write ONCE (never overwritten).
    const int rx = tid & 7;
    const uint32_t rowo = (uint32_t)tid * 128u;
    {
        const uint32_t off7 = rowo + ((uint32_t)(7 ^ rx) << 4);
        *(uint4*)(Ahi + off7) = make_uint4(0u, 0u, 0u, 0u);
        *(uint4*)(Alo + off7) = make_uint4(0u, 0u, 0u, 0u);
    }

    for (int t = 0; t < TPC; t++) {
        const int p = (blockIdx.x * TPC + t) * 128 + tid;
        const int x = p & (WDIM - 1);
        const int y = p >> 10;

        float tt = __ldg(&rot[p]) / TP * 4.0f;
        const int dd = ((int)tt) & 3;
        const int rb0 = dd & 1, rb1 = (dd >> 1) & 1;

        // UNROTATED gather addresses (coalesced), rotate in registers.
        int idx[9];
#pragma unroll
        for (int j = 0; j < 9; j++) {
            const int dy0 = j / 3 - 1, dx0 = j % 3 - 1;
            idx[j] = (((y + dy0) & (WDIM - 1)) << 10) + ((x + dx0) & (WDIM - 1));
        }

        const int T1[9] = {6,3,0,7,4,1,8,5,2};
        const int T3[9] = {2,5,8,1,4,7,0,3,6};

        // Streamed hi/lo pack into swizzled A-tile rows (no a[54] buffer).
        float ph = 0.0f, pl = 0.0f;
        uint32_t chh[4], cll[4];
#pragma unroll
        for (int c = 0; c < 6; c++) {
            const float* __restrict__ chp =
                (c == 0) ? se : (c == 1) ? te : (c == 2) ? sr : hc + (c - 3) * NPIX;
            float pr[9];
#pragma unroll
            for (int j = 0; j < 9; j++) pr[j] = __ldg(&chp[idx[j]]);
#pragma unroll
            for (int j = 0; j < 9; j++) {
                float v01 = rb0 ? pr[T1[j]] : pr[j];
                float v23 = rb0 ? pr[T3[j]] : pr[8 - j];
                float v = rb1 ? v23 : v01;
                const int k = c * 9 + j;            // compile-time K position
                float hv = bt(v);
                float lv = v - hv;
                if ((k & 1) == 0) { ph = hv; pl = lv; }
                else {
                    const int w = (k & 7) >> 1;
                    chh[w] = pk(ph, hv);
                    cll[w] = pk(pl, lv);
                    if ((k & 7) == 7) {
                        const uint32_t off = rowo + ((uint32_t)((k >> 3) ^ rx) << 4);
                        *(uint4*)(Ahi + off) = make_uint4(chh[0], chh[1], chh[2], chh[3]);
                        *(uint4*)(Alo + off) = make_uint4(cll[0], cll[1], cll[2], cll[3]);
                    }
                }
            }
        }
        {   // finish chunk 6: K=54 bias (=1 exact), K=55 pad
            chh[3] = pk(1.0f, 0.0f);
            cll[3] = 0u;
            const uint32_t off6 = rowo + ((uint32_t)(6 ^ rx) << 4);
            *(uint4*)(Ahi + off6) = make_uint4(chh[0], chh[1], chh[2], chh[3]);
            *(uint4*)(Alo + off6) = make_uint4(cll[0], cll[1], cll[2], cll[3]);
        }
        __syncwarp();

        // ---- per-warp MMA over its 32 rows (two 16-row subtiles) ----
#pragma unroll
        for (int smt = 0; smt < 2; smt++) {
            const int rl = wid * 32 + smt * 16 + (lane & 15);
            const uint32_t rbase = (uint32_t)rl * 128u;
            const int rrx = rl & 7;
            const int sel = lane >> 4;

            uint32_t af[4][4];
#pragma unroll
            for (int kt = 0; kt < 4; kt++)
                ldm4(af[kt], sAhi + rbase + ((uint32_t)((kt * 2 + sel) ^ rrx) << 4));

            float d1[4][4];
#pragma unroll
            for (int nt = 0; nt < 4; nt++)
#pragma unroll
                for (int u = 0; u < 4; u++) d1[nt][u] = 0.0f;

#pragma unroll
            for (int nt = 0; nt < 4; nt++) {
#pragma unroll
                for (int kt = 0; kt < 3; kt++) {
                    mma16816(d1[nt], af[kt], w1h[kt][nt][0], w1h[kt][nt][1]);          // Ah*Wh
                    mma16816(d1[nt], af[kt], w1lo[kt * 4 + nt].x, w1lo[kt * 4 + nt].y);// Ah*Wl
                }
                mma16808(d1[nt], af[3][0], af[3][1], w1h[3][nt][0]);        // kt3 (K48-55)
                mma16808(d1[nt], af[3][0], af[3][1], w1lo[12 + nt].x);
            }
#pragma unroll
            for (int kt = 0; kt < 4; kt++)
                ldm4(af[kt], sAlo + rbase + ((uint32_t)((kt * 2 + sel) ^ rrx) << 4));
#pragma unroll
            for (int nt = 0; nt < 4; nt++) {
#pragma unroll
                for (int kt = 0; kt < 3; kt++)
                    mma16816(d1[nt], af[kt], w1h[kt][nt][0], w1h[kt][nt][1]);          // Al*Wh
                mma16808(d1[nt], af[3][0], af[3][1], w1h[3][nt][0]);
            }

            // ---- ReLU + hi/lo split -> layer-2 A fragments, register-resident ----
            uint32_t a2h[2][4], a2l[2][4];
#pragma unroll
            for (int kt2 = 0; kt2 < 2; kt2++) {
#pragma unroll
                for (int hh = 0; hh < 2; hh++) {     // D1 n-tile = 2*kt2 + hh
                    float* e = d1[2 * kt2 + hh];
                    float r0 = fmaxf(e[0], 0.0f), r1 = fmaxf(e[1], 0.0f);
                    float r2 = fmaxf(e[2], 0.0f), r3 = fmaxf(e[3], 0.0f);
                    float t0 = bt(r0), t1 = bt(r1), t2 = bt(r2), t3 = bt(r3);
                    a2h[kt2][hh * 2 + 0] = pk(t0, t1);
                    a2h[kt2][hh * 2 + 1] = pk(t2, t3);
                    a2l[kt2][hh * 2 + 0] = pk(r0 - t0, r1 - t1);
                    a2l[kt2][hh * 2 + 1] = pk(r2 - t2, r3 - t3);
                }
            }

            float d2[2][4];
#pragma unroll
            for (int nt2 = 0; nt2 < 2; nt2++)
#pragma unroll
                for (int u = 0; u < 4; u++) d2[nt2][u] = 0.0f;

#pragma unroll
            for (int nt2 = 0; nt2 < 2; nt2++)
#pragma unroll
            for (int kt2 = 0; kt2 < 2; kt2++) {
                uint2 bh = W2H[(kt2 * 2 + nt2) * 32 + lane];
                uint2 bl = W2L[(kt2 * 2 + nt2) * 32 + lane];
                mma16816(d2[nt2], a2h[kt2], bh.x, bh.y);
                mma16816(d2[nt2], a2h[kt2], bl.x, bl.y);
                mma16816(d2[nt2], a2l[kt2], bh.x, bh.y);
            }

            const int r0w = wid * 32 + smt * 16 + nrow;
#pragma unroll
            for (int nt2 = 0; nt2 < 2; nt2++) {
                const int col = nt2 * 8 + q * 2;
                ZS[r0w * 17 + col]           = d2[nt2][0];
                ZS[r0w * 17 + col + 1]       = d2[nt2][1];
                ZS[(r0w + 8) * 17 + col]     = d2[nt2][2];
                ZS[(r0w + 8) * 17 + col + 1] = d2[nt2][3];
            }
        }
        __syncwarp();

        float z[13];
#pragma unroll
        for (int m = 0; m < 13; m++) z[m] = ZS[tid * 17 + m] + B2S[m];
        epilogue(z, dd, p, out);
        __syncwarp();
    }
}

extern "C" void kernel_launch(void* const* d_in, const int* in_sizes, int n_in,
                              void* d_out, int out_size)
{
    const float* se  = (const float*)d_in[0];
    const float* te  = (const float*)d_in[1];
    const float* sr  = (const float*)d_in[2];
    const float* hc  = (const float*)d_in[3];
    const float* rot = (const float*)d_in[4];
    const float* w1  = (const float*)d_in[5];
    const float* b1  = (const float*)d_in[6];
    const float* w2  = (const float*)d_in[7];
    const float* b2  = (const float*)d_in[8];
    float* out = (float*)d_out;

    energy_cnn_hmma_kernel<<<NCTA, 128>>>(se, te, sr, hc, rot, w1, b1, w2, b2, out);
}

// round 16
// speedup vs baseline: 1.1167x; 1.0649x over previous
#include <cuda_runtime.h>
#include <cuda_bf16.h>
#include <cstdint>

#define WDIM 1024
#define NPIX (WDIM * WDIM)
#define TPC 4
#define NCTA (NPIX / 128 / TPC)   // 2048

static __device__ __forceinline__ float bt(float v) {
    return __bfloat162float(__float2bfloat16_rn(v));
}
static __device__ __forceinline__ uint32_t pk(float lo, float hi) {
    uint32_t r;
    asm("cvt.rn.bf16x2.f32 %0, %1, %2;" : "=r"(r) : "f"(hi), "f"(lo));
    return r;
}
static __device__ __forceinline__ uint32_t smem_u32(const void* p) {
    uint32_t a;
    asm("{ .reg .u64 t; cvta.to.shared.u64 t, %1; cvt.u32.u64 %0, t; }" : "=r"(a) : "l"(p));
    return a;
}
static __device__ __forceinline__ void mma16816(float* d, const uint32_t* a,
                                                uint32_t b0, uint32_t b1) {
    asm volatile(
        "mma.sync.aligned.m16n8k16.row.col.f32.bf16.bf16.f32 "
        "{%0,%1,%2,%3}, {%4,%5,%6,%7}, {%8,%9}, {%0,%1,%2,%3};"
        : "+f"(d[0]), "+f"(d[1]), "+f"(d[2]), "+f"(d[3])
        : "r"(a[0]), "r"(a[1]), "r"(a[2]), "r"(a[3]), "r"(b0), "r"(b1));
}
static __device__ __forceinline__ void mma16808(float* d, uint32_t a0, uint32_t a1,
                                                uint32_t b0) {
    asm volatile(
        "mma.sync.aligned.m16n8k8.row.col.f32.bf16.bf16.f32 "
        "{%0,%1,%2,%3}, {%4,%5}, {%6}, {%0,%1,%2,%3};"
        : "+f"(d[0]), "+f"(d[1]), "+f"(d[2]), "+f"(d[3])
        : "r"(a0), "r"(a1), "r"(b0));
}
static __device__ __forceinline__ void ldm4(uint32_t* r, uint32_t addr) {
    asm volatile("ldmatrix.sync.aligned.m8n8.x4.shared.b16 {%0,%1,%2,%3}, [%4];"
                 : "=r"(r[0]), "=r"(r[1]), "=r"(r[2]), "=r"(r[3]) : "r"(addr));
}

// softmax(9) + inverse rotation (register selects) + tanh + sigmoid; coalesced stores.
static __device__ __forceinline__ void epilogue(const float* z, int d, int p,
                                                float* __restrict__ out)
{
    const int rb0 = d & 1;
    const int rb1 = (d >> 1) & 1;

    float mx = z[0];
#pragma unroll
    for (int j = 1; j < 9; j++) mx = fmaxf(mx, z[j]);
    float s[9];
    float sum = 0.0f;
#pragma unroll
    for (int j = 0; j < 9; j++) { s[j] = __expf(z[j] - mx); sum += s[j]; }
    float inv = __fdividef(1.0f, sum);

    const int I0[9] = {0,1,2,3,4,5,6,7,8};
    const int I1[9] = {2,5,8,1,4,7,0,3,6};
    const int I2[9] = {8,7,6,5,4,3,2,1,0};
    const int I3[9] = {6,3,0,7,4,1,8,5,2};
#pragma unroll
    for (int m = 0; m < 9; m++) {
        float v01 = rb0 ? s[I1[m]] : s[I0[m]];
        float v23 = rb0 ? s[I3[m]] : s[I2[m]];
        float v = rb1 ? v23 : v01;
        out[m * NPIX + p] = v * inv;
    }
    out[9 * NPIX + p] = tanhf(z[9]);
#pragma unroll
    for (int m = 0; m < 3; m++)
        out[(10 + m) * NPIX + p] = __fdividef(1.0f, 1.0f + __expf(-z[10 + m]));
}

__global__ void __launch_bounds__(128, 4) energy_cnn_hmma_kernel(
    const float* __restrict__ se, const float* __restrict__ te,
    const float* __restrict__ sr, const float* __restrict__ hc,
    const float* __restrict__ rot, const float* __restrict__ w1,
    const float* __restrict__ b1, const float* __restrict__ w2,
    const float* __restrict__ b2, float* __restrict__ out)
{
    // A tiles: 128 rows x 64 bf16 (128B rows), XOR-16B-chunk swizzle.
    __shared__ __align__(128) uint8_t Ahi[128 * 128];
    __shared__ __align__(128) uint8_t Alo[128 * 128];
    // fragment banks [frag][lane] (conflict-free broadcast layout).
    __shared__ __align__(16) uint2 W1LO[12 * 32];      // kt 0..2
    __shared__ __align__(16) uint32_t W1LO3[4 * 32];   // kt 3, reg0 only
    __shared__ __align__(16) uint2 W2H[4 * 32];
    __shared__ __align__(16) uint2 W2L[4 * 32];
    __shared__ float B2S[13];
    // z staging, pitch 17 floats (conflict-free column reads).
    __shared__ float ZS[128 * 17];

    const int tid = threadIdx.x;
    const int lane = tid & 31, wid = tid >> 5;
    const int q = lane & 3, nrow = lane >> 2;

    // ---- w1-hi fragments in registers (28 regs); lo / w2 into smem banks ----
    uint32_t w1h[3][4][2];   // kt 0..2
    uint32_t w1h3[4];        // kt 3, reg0 (K48-55; K56-63 are zero)
#pragma unroll
    for (int kt = 0; kt < 4; kt++)
#pragma unroll
    for (int nt = 0; nt < 4; nt++) {
        const int n = nt * 8 + nrow;
        const int k0 = kt * 16 + q * 2;
        float v[4];
#pragma unroll
        for (int u = 0; u < 4; u++) {
            int k = k0 + (u >> 1) * 8 + (u & 1);
            v[u] = (k < 54) ? __ldg(&w1[n * 54 + k]) : ((k == 54) ? __ldg(&b1[n]) : 0.0f);
        }
        float h0 = bt(v[0]), h1 = bt(v[1]), h2 = bt(v[2]), h3 = bt(v[3]);
        if (kt < 3) {
            w1h[kt][nt][0] = pk(h0, h1);
            w1h[kt][nt][1] = pk(h2, h3);
            if (wid == 0)
                W1LO[(kt * 4 + nt) * 32 + lane] =
                    make_uint2(pk(v[0] - h0, v[1] - h1), pk(v[2] - h2, v[3] - h3));
        } else {
            w1h3[nt] = pk(h0, h1);
            if (wid == 0)
                W1LO3[nt * 32 + lane] = pk(v[0] - h0, v[1] - h1);
        }
    }
    if (wid == 0) {
#pragma unroll
        for (int kt = 0; kt < 2; kt++)
#pragma unroll
        for (int nt = 0; nt < 2; nt++) {
            const int n = nt * 8 + nrow;
            const int k0 = kt * 16 + q * 2;
            float v[4];
#pragma unroll
            for (int u = 0; u < 4; u++) {
                int k = k0 + (u >> 1) * 8 + (u & 1);
                v[u] = (n < 13) ? __ldg(&w2[n * 32 + k]) : 0.0f;
            }
            float h0 = bt(v[0]), h1 = bt(v[1]), h2 = bt(v[2]), h3 = bt(v[3]);
            W2H[(kt * 2 + nt) * 32 + lane] = make_uint2(pk(h0, h1), pk(h2, h3));
            W2L[(kt * 2 + nt) * 32 + lane] =
                make_uint2(pk(v[0] - h0, v[1] - h1), pk(v[2] - h2, v[3] - h3));
        }
    }
    if (tid < 13) B2S[tid] = b2[tid];
    __syncthreads();

    const uint32_t sAhi = smem_u32(Ahi), sAlo = smem_u32(Alo);
    const float* chans[6] = { se, te, sr, hc, hc + NPIX, hc + 2 * NPIX };
    const float TP = 6.2831853071795864f;

    // Constant zero chunk 7 of each A-tile row: write ONCE.
    const int rx = tid & 7;
    const uint32_t rowo = (uint32_t)tid * 128u;
    {
        const uint32_t off7 = rowo + ((uint32_t)(7 ^ rx) << 4);
        *(uint4*)(Ahi + off7) = make_uint4(0u, 0u, 0u, 0u);
        *(uint4*)(Alo + off7) = make_uint4(0u, 0u, 0u, 0u);
    }

    // Subtile row addressing (fixed per thread).
    const int rl0 = wid * 32 + (lane & 15);
    const int rl1 = rl0 + 16;
    const uint32_t rb0a = (uint32_t)rl0 * 128u, rb1a = (uint32_t)rl1 * 128u;
    const int rrx0 = rl0 & 7, rrx1 = rl1 & 7;
    const int sel = lane >> 4;

    for (int t = 0; t < TPC; t++) {
        const int p = (blockIdx.x * TPC + t) * 128 + tid;
        const int x = p & (WDIM - 1);
        const int y = p >> 10;

        float tt = __ldg(&rot[p]) / TP * 4.0f;
        const int dd = ((int)tt) & 3;
        const int prb0 = dd & 1, prb1 = (dd >> 1) & 1;

        // UNROTATED gather addresses (coalesced), rotate in registers.
        int idx[9];
#pragma unroll
        for (int j = 0; j < 9; j++) {
            const int dy0 = j / 3 - 1, dx0 = j % 3 - 1;
            idx[j] = (((y + dy0) & (WDIM - 1)) << 10) + ((x + dx0) & (WDIM - 1));
        }

        const int T1[9] = {6,3,0,7,4,1,8,5,2};
        const int T3[9] = {2,5,8,1,4,7,0,3,6};

        // Streamed hi/lo pack into swizzled A-tile rows.
        float ph = 0.0f, pl = 0.0f;
        uint32_t chh[4], cll[4];
#pragma unroll
        for (int c = 0; c < 6; c++) {
            const float* __restrict__ chp = chans[c];
            float pr[9];
#pragma unroll
            for (int j = 0; j < 9; j++) pr[j] = __ldg(&chp[idx[j]]);
#pragma unroll
            for (int j = 0; j < 9; j++) {
                float v01 = prb0 ? pr[T1[j]] : pr[j];
                float v23 = prb0 ? pr[T3[j]] : pr[8 - j];
                float v = prb1 ? v23 : v01;
                const int k = c * 9 + j;            // compile-time K position
                float hv = bt(v);
                float lv = v - hv;
                if ((k & 1) == 0) { ph = hv; pl = lv; }
                else {
                    const int w = (k & 7) >> 1;
                    chh[w] = pk(ph, hv);
                    cll[w] = pk(pl, lv);
                    if ((k & 7) == 7) {
                        const uint32_t off = rowo + ((uint32_t)((k >> 3) ^ rx) << 4);
                        *(uint4*)(Ahi + off) = make_uint4(chh[0], chh[1], chh[2], chh[3]);
                        *(uint4*)(Alo + off) = make_uint4(cll[0], cll[1], cll[2], cll[3]);
                    }
                }
            }
        }
        {   // finish chunk 6: K=54 bias (=1 exact), K=55 pad
            chh[3] = pk(1.0f, 0.0f);
            cll[3] = 0u;
            const uint32_t off6 = rowo + ((uint32_t)(6 ^ rx) << 4);
            *(uint4*)(Ahi + off6) = make_uint4(chh[0], chh[1], chh[2], chh[3]);
            *(uint4*)(Alo + off6) = make_uint4(cll[0], cll[1], cll[2], cll[3]);
        }
        __syncwarp();

        // ---- layer 1: both 16-row subtiles processed per (kt,nt) so each
        //      bank fragment is loaded ONCE per tile ----
        float d1[2][4][4];
#pragma unroll
        for (int s = 0; s < 2; s++)
#pragma unroll
        for (int nt = 0; nt < 4; nt++)
#pragma unroll
            for (int u = 0; u < 4; u++) d1[s][nt][u] = 0.0f;

        // terms 1+2: Ah*Wh + Ah*Wl
#pragma unroll
        for (int kt = 0; kt < 4; kt++) {
            uint32_t af0[4], af1[4];
            ldm4(af0, sAhi + rb0a + ((uint32_t)((kt * 2 + sel) ^ rrx0) << 4));
            ldm4(af1, sAhi + rb1a + ((uint32_t)((kt * 2 + sel) ^ rrx1) << 4));
            if (kt < 3) {
#pragma unroll
                for (int nt = 0; nt < 4; nt++) {
                    uint2 fb = W1LO[(kt * 4 + nt) * 32 + lane];
                    mma16816(d1[0][nt], af0, w1h[kt][nt][0], w1h[kt][nt][1]);
                    mma16816(d1[0][nt], af0, fb.x, fb.y);
                    mma16816(d1[1][nt], af1, w1h[kt][nt][0], w1h[kt][nt][1]);
                    mma16816(d1[1][nt], af1, fb.x, fb.y);
                }
            } else {
#pragma unroll
                for (int nt = 0; nt < 4; nt++) {
                    uint32_t fl = W1LO3[nt * 32 + lane];
                    mma16808(d1[0][nt], af0[0], af0[1], w1h3[nt]);
                    mma16808(d1[0][nt], af0[0], af0[1], fl);
                    mma16808(d1[1][nt], af1[0], af1[1], w1h3[nt]);
                    mma16808(d1[1][nt], af1[0], af1[1], fl);
                }
            }
        }
        // term 3: Al*Wh (w1h already in registers, no bank reads)
#pragma unroll
        for (int kt = 0; kt < 4; kt++) {
            uint32_t af0[4], af1[4];
            ldm4(af0, sAlo + rb0a + ((uint32_t)((kt * 2 + sel) ^ rrx0) << 4));
            ldm4(af1, sAlo + rb1a + ((uint32_t)((kt * 2 + sel) ^ rrx1) << 4));
            if (kt < 3) {
#pragma unroll
                for (int nt = 0; nt < 4; nt++) {
                    mma16816(d1[0][nt], af0, w1h[kt][nt][0], w1h[kt][nt][1]);
                    mma16816(d1[1][nt], af1, w1h[kt][nt][0], w1h[kt][nt][1]);
                }
            } else {
#pragma unroll
                for (int nt = 0; nt < 4; nt++) {
                    mma16808(d1[0][nt], af0[0], af0[1], w1h3[nt]);
                    mma16808(d1[1][nt], af1[0], af1[1], w1h3[nt]);
                }
            }
        }

        // ---- ReLU + hi/lo split -> layer-2 A fragments (per subtile) ----
        uint32_t a2h[2][2][4], a2l[2][2][4];
#pragma unroll
        for (int s = 0; s < 2; s++)
#pragma unroll
        for (int kt2 = 0; kt2 < 2; kt2++) {
#pragma unroll
            for (int hh = 0; hh < 2; hh++) {         // D1 n-tile = 2*kt2 + hh
                float* e = d1[s][2 * kt2 + hh];
                float r0 = fmaxf(e[0], 0.0f), r1 = fmaxf(e[1], 0.0f);
                float r2 = fmaxf(e[2], 0.0f), r3 = fmaxf(e[3], 0.0f);
                float t0 = bt(r0), t1 = bt(r1), t2 = bt(r2), t3 = bt(r3);
                a2h[s][kt2][hh * 2 + 0] = pk(t0, t1);
                a2h[s][kt2][hh * 2 + 1] = pk(t2, t3);
                a2l[s][kt2][hh * 2 + 0] = pk(r0 - t0, r1 - t1);
                a2l[s][kt2][hh * 2 + 1] = pk(r2 - t2, r3 - t3);
            }
        }

        // ---- layer 2: w2 bank fragments loaded once per tile ----
        float d2[2][2][4];
#pragma unroll
        for (int s = 0; s < 2; s++)
#pragma unroll
        for (int nt2 = 0; nt2 < 2; nt2++)
#pragma unroll
            for (int u = 0; u < 4; u++) d2[s][nt2][u] = 0.0f;

#pragma unroll
        for (int kt2 = 0; kt2 < 2; kt2++)
#pragma unroll
        for (int nt2 = 0; nt2 < 2; nt2++) {
            uint2 bh = W2H[(kt2 * 2 + nt2) * 32 + lane];
            uint2 bl = W2L[(kt2 * 2 + nt2) * 32 + lane];
#pragma unroll
            for (int s = 0; s < 2; s++) {
                mma16816(d2[s][nt2], a2h[s][kt2], bh.x, bh.y);
                mma16816(d2[s][nt2], a2h[s][kt2], bl.x, bl.y);
                mma16816(d2[s][nt2], a2l[s][kt2], bh.x, bh.y);
            }
        }

        // ---- stage z to ZS ----
#pragma unroll
        for (int s = 0; s < 2; s++) {
            const int r0w = wid * 32 + s * 16 + nrow;
#pragma unroll
            for (int nt2 = 0; nt2 < 2; nt2++) {
                const int col = nt2 * 8 + q * 2;
                ZS[r0w * 17 + col]           = d2[s][nt2][0];
                ZS[r0w * 17 + col + 1]       = d2[s][nt2][1];
                ZS[(r0w + 8) * 17 + col]     = d2[s][nt2][2];
                ZS[(r0w + 8) * 17 + col + 1] = d2[s][nt2][3];
            }
        }
        __syncwarp();

        float z[13];
#pragma unroll
        for (int m = 0; m < 13; m++) z[m] = ZS[tid * 17 + m] + B2S[m];
        epilogue(z, dd, p, out);
        __syncwarp();
    }
}

extern "C" void kernel_launch(void* const* d_in, const int* in_sizes, int n_in,
                              void* d_out, int out_size)
{
    const float* se  = (const float*)d_in[0];
    const float* te  = (const float*)d_in[1];
    const float* sr  = (const float*)d_in[2];
    const float* hc  = (const float*)d_in[3];
    const float* rot = (const float*)d_in[4];
    const float* w1  = (const float*)d_in[5];
    const float* b1  = (const float*)d_in[6];
    const float* w2  = (const float*)d_in[7];
    const float* b2  = (const float*)d_in[8];
    float* out = (float*)d_out;

    energy_cnn_hmma_kernel<<<NCTA, 128>>>(se, te, sr, hc, rot, w1, b1, w2, b2, out);
}

// round 17
// speedup vs baseline: 1.2512x; 1.1204x over previous
#include <cuda_runtime.h>
#include <cuda_bf16.h>
#include <cstdint>

#define WDIM 1024
#define NPIX (WDIM * WDIM)
#define TPC 4
#define NCTA (NPIX / 128 / TPC)   // 2048

static __device__ __forceinline__ float bt(float v) {
    return __bfloat162float(__float2bfloat16_rn(v));
}
static __device__ __forceinline__ uint32_t pk(float lo, float hi) {
    uint32_t r;
    asm("cvt.rn.bf16x2.f32 %0, %1, %2;" : "=r"(r) : "f"(hi), "f"(lo));
    return r;
}
static __device__ __forceinline__ uint32_t smem_u32(const void* p) {
    uint32_t a;
    asm("{ .reg .u64 t; cvta.to.shared.u64 t, %1; cvt.u32.u64 %0, t; }" : "=r"(a) : "l"(p));
    return a;
}
static __device__ __forceinline__ void mma16816(float* d, const uint32_t* a,
                                                uint32_t b0, uint32_t b1) {
    asm volatile(
        "mma.sync.aligned.m16n8k16.row.col.f32.bf16.bf16.f32 "
        "{%0,%1,%2,%3}, {%4,%5,%6,%7}, {%8,%9}, {%0,%1,%2,%3};"
        : "+f"(d[0]), "+f"(d[1]), "+f"(d[2]), "+f"(d[3])
        : "r"(a[0]), "r"(a[1]), "r"(a[2]), "r"(a[3]), "r"(b0), "r"(b1));
}
static __device__ __forceinline__ void mma16808(float* d, uint32_t a0, uint32_t a1,
                                                uint32_t b0) {
    asm volatile(
        "mma.sync.aligned.m16n8k8.row.col.f32.bf16.bf16.f32 "
        "{%0,%1,%2,%3}, {%4,%5}, {%6}, {%0,%1,%2,%3};"
        : "+f"(d[0]), "+f"(d[1]), "+f"(d[2]), "+f"(d[3])
        : "r"(a0), "r"(a1), "r"(b0));
}
static __device__ __forceinline__ void ldm4(uint32_t* r, uint32_t addr) {
    asm volatile("ldmatrix.sync.aligned.m8n8.x4.shared.b16 {%0,%1,%2,%3}, [%4];"
                 : "=r"(r[0]), "=r"(r[1]), "=r"(r[2]), "=r"(r[3]) : "r"(addr));
}
static __device__ __forceinline__ void ldm2(uint32_t* r, uint32_t addr) {
    asm volatile("ldmatrix.sync.aligned.m8n8.x2.shared.b16 {%0,%1}, [%2];"
                 : "=r"(r[0]), "=r"(r[1]) : "r"(addr));
}

// softmax(9) + inverse rotation (register selects) + tanh + sigmoid; coalesced stores.
static __device__ __forceinline__ void epilogue(const float* z, int d, int p,
                                                float* __restrict__ out)
{
    const int rb0 = d & 1;
    const int rb1 = (d >> 1) & 1;

    float mx = z[0];
#pragma unroll
    for (int j = 1; j < 9; j++) mx = fmaxf(mx, z[j]);
    float s[9];
    float sum = 0.0f;
#pragma unroll
    for (int j = 0; j < 9; j++) { s[j] = __expf(z[j] - mx); sum += s[j]; }
    float inv = __fdividef(1.0f, sum);

    const int I0[9] = {0,1,2,3,4,5,6,7,8};
    const int I1[9] = {2,5,8,1,4,7,0,3,6};
    const int I2[9] = {8,7,6,5,4,3,2,1,0};
    const int I3[9] = {6,3,0,7,4,1,8,5,2};
#pragma unroll
    for (int m = 0; m < 9; m++) {
        float v01 = rb0 ? s[I1[m]] : s[I0[m]];
        float v23 = rb0 ? s[I3[m]] : s[I2[m]];
        float v = rb1 ? v23 : v01;
        out[m * NPIX + p] = v * inv;
    }
    out[9 * NPIX + p] = tanhf(z[9]);
#pragma unroll
    for (int m = 0; m < 3; m++)
        out[(10 + m) * NPIX + p] = __fdividef(1.0f, 1.0f + __expf(-z[10 + m]));
}

__global__ void __launch_bounds__(128, 5) energy_cnn_hmma_kernel(
    const float* __restrict__ se, const float* __restrict__ te,
    const float* __restrict__ sr, const float* __restrict__ hc,
    const float* __restrict__ rot, const float* __restrict__ w1,
    const float* __restrict__ b1, const float* __restrict__ w2,
    const float* __restrict__ b2, float* __restrict__ out)
{
    // A tiles: 128 rows x 64 bf16 (128B rows), XOR-16B-chunk swizzle.
    // ZS (z staging) OVERLAYS Alo: each warp's 32x17 float block lives in its
    // own warp-private Alo quarter (2176B < 4096B); chunks 0-6 are rewritten
    // every tile and chunk 7 is never read (kt3 uses ldmatrix.x2).
    __shared__ __align__(128) uint8_t Ahi[128 * 128];
    __shared__ __align__(128) uint8_t Alo[128 * 128];
    // fragment banks [frag][lane] (conflict-free broadcast layout).
    __shared__ __align__(16) uint2 W1H[12 * 32];       // kt 0..2 hi
    __shared__ __align__(16) uint32_t W1H3[4 * 32];    // kt 3 hi, reg0 only
    __shared__ __align__(16) uint2 W1LO[12 * 32];      // kt 0..2 lo
    __shared__ __align__(16) uint32_t W1LO3[4 * 32];   // kt 3 lo, reg0 only
    __shared__ __align__(16) uint2 W2H[4 * 32];
    __shared__ __align__(16) uint2 W2L[4 * 32];
    __shared__ float B2S[13];

    const int tid = threadIdx.x;
    const int lane = tid & 31, wid = tid >> 5;
    const int q = lane & 3, nrow = lane >> 2;

    // ---- build ALL fragment banks (warp 0 only; zero permanent frag regs) ----
    if (wid == 0) {
#pragma unroll
        for (int kt = 0; kt < 4; kt++)
#pragma unroll
        for (int nt = 0; nt < 4; nt++) {
            const int n = nt * 8 + nrow;
            const int k0 = kt * 16 + q * 2;
            float v[4];
#pragma unroll
            for (int u = 0; u < 4; u++) {
                int k = k0 + (u >> 1) * 8 + (u & 1);
                v[u] = (k < 54) ? __ldg(&w1[n * 54 + k]) : ((k == 54) ? __ldg(&b1[n]) : 0.0f);
            }
            float h0 = bt(v[0]), h1 = bt(v[1]), h2 = bt(v[2]), h3 = bt(v[3]);
            if (kt < 3) {
                W1H[(kt * 4 + nt) * 32 + lane] = make_uint2(pk(h0, h1), pk(h2, h3));
                W1LO[(kt * 4 + nt) * 32 + lane] =
                    make_uint2(pk(v[0] - h0, v[1] - h1), pk(v[2] - h2, v[3] - h3));
            } else {
                W1H3[nt * 32 + lane] = pk(h0, h1);
                W1LO3[nt * 32 + lane] = pk(v[0] - h0, v[1] - h1);
            }
        }
#pragma unroll
        for (int kt = 0; kt < 2; kt++)
#pragma unroll
        for (int nt = 0; nt < 2; nt++) {
            const int n = nt * 8 + nrow;
            const int k0 = kt * 16 + q * 2;
            float v[4];
#pragma unroll
            for (int u = 0; u < 4; u++) {
                int k = k0 + (u >> 1) * 8 + (u & 1);
                v[u] = (n < 13) ? __ldg(&w2[n * 32 + k]) : 0.0f;
            }
            float h0 = bt(v[0]), h1 = bt(v[1]), h2 = bt(v[2]), h3 = bt(v[3]);
            W2H[(kt * 2 + nt) * 32 + lane] = make_uint2(pk(h0, h1), pk(h2, h3));
            W2L[(kt * 2 + nt) * 32 + lane] =
                make_uint2(pk(v[0] - h0, v[1] - h1), pk(v[2] - h2, v[3] - h3));
        }
    }
    if (tid < 13) B2S[tid] = b2[tid];
    __syncthreads();

    const uint32_t sAhi = smem_u32(Ahi), sAlo = smem_u32(Alo);
    const float* chans[6] = { se, te, sr, hc, hc + NPIX, hc + 2 * NPIX };
    const float TP = 6.2831853071795864f;

    const int rx = tid & 7;
    const uint32_t rowo = (uint32_t)tid * 128u;

    // Subtile row addressing (fixed per thread).
    const int rl0 = wid * 32 + (lane & 15);
    const int rl1 = rl0 + 16;
    const uint32_t rb0a = (uint32_t)rl0 * 128u, rb1a = (uint32_t)rl1 * 128u;
    const int rrx0 = rl0 & 7, rrx1 = rl1 & 7;
    const int sel = lane >> 4;
    float* zsp = (float*)(Alo + ((uint32_t)wid << 12));   // warp-private ZS overlay

    for (int t = 0; t < TPC; t++) {
        const int p = (blockIdx.x * TPC + t) * 128 + tid;
        const int x = p & (WDIM - 1);
        const int y = p >> 10;

        float tt = __ldg(&rot[p]) / TP * 4.0f;
        const int dd = ((int)tt) & 3;
        const int prb0 = dd & 1, prb1 = (dd >> 1) & 1;

        // UNROTATED gather addresses (coalesced), rotate in registers.
        int idx[9];
#pragma unroll
        for (int j = 0; j < 9; j++) {
            const int dy0 = j / 3 - 1, dx0 = j % 3 - 1;
            idx[j] = (((y + dy0) & (WDIM - 1)) << 10) + ((x + dx0) & (WDIM - 1));
        }

        const int T1[9] = {6,3,0,7,4,1,8,5,2};
        const int T3[9] = {2,5,8,1,4,7,0,3,6};

        // Streamed hi/lo pack into swizzled A-tile rows (chunks 0..6 only).
        float ph = 0.0f, pl = 0.0f;
        uint32_t chh[4], cll[4];
#pragma unroll
        for (int c = 0; c < 6; c++) {
            const float* __restrict__ chp = chans[c];
            float pr[9];
#pragma unroll
            for (int j = 0; j < 9; j++) pr[j] = __ldg(&chp[idx[j]]);
#pragma unroll
            for (int j = 0; j < 9; j++) {
                float v01 = prb0 ? pr[T1[j]] : pr[j];
                float v23 = prb0 ? pr[T3[j]] : pr[8 - j];
                float v = prb1 ? v23 : v01;
                const int k = c * 9 + j;            // compile-time K position
                float hv = bt(v);
                float lv = v - hv;
                if ((k & 1) == 0) { ph = hv; pl = lv; }
                else {
                    const int w = (k & 7) >> 1;
                    chh[w] = pk(ph, hv);
                    cll[w] = pk(pl, lv);
                    if ((k & 7) == 7) {
                        const uint32_t off = rowo + ((uint32_t)((k >> 3) ^ rx) << 4);
                        *(uint4*)(Ahi + off) = make_uint4(chh[0], chh[1], chh[2], chh[3]);
                        *(uint4*)(Alo + off) = make_uint4(cll[0], cll[1], cll[2], cll[3]);
                    }
                }
            }
        }
        {   // finish chunk 6: K=54 bias (=1 exact), K=55 pad
            chh[3] = pk(1.0f, 0.0f);
            cll[3] = 0u;
            const uint32_t off6 = rowo + ((uint32_t)(6 ^ rx) << 4);
            *(uint4*)(Ahi + off6) = make_uint4(chh[0], chh[1], chh[2], chh[3]);
            *(uint4*)(Alo + off6) = make_uint4(cll[0], cll[1], cll[2], cll[3]);
        }
        __syncwarp();

        // ---- layer 1: all 3 precision terms per kt, both subtiles, each
        //      bank fragment and A fragment loaded ONCE per tile ----
        float d1[2][4][4];
#pragma unroll
        for (int s = 0; s < 2; s++)
#pragma unroll
        for (int nt = 0; nt < 4; nt++)
#pragma unroll
            for (int u = 0; u < 4; u++) d1[s][nt][u] = 0.0f;

#pragma unroll
        for (int kt = 0; kt < 3; kt++) {
            uint32_t ah0[4], ah1[4], al0[4], al1[4];
            ldm4(ah0, sAhi + rb0a + ((uint32_t)((kt * 2 + sel) ^ rrx0) << 4));
            ldm4(ah1, sAhi + rb1a + ((uint32_t)((kt * 2 + sel) ^ rrx1) << 4));
            ldm4(al0, sAlo + rb0a + ((uint32_t)((kt * 2 + sel) ^ rrx0) << 4));
            ldm4(al1, sAlo + rb1a + ((uint32_t)((kt * 2 + sel) ^ rrx1) << 4));
#pragma unroll
            for (int nt = 0; nt < 4; nt++) {
                uint2 bh = W1H[(kt * 4 + nt) * 32 + lane];
                uint2 bl = W1LO[(kt * 4 + nt) * 32 + lane];
                mma16816(d1[0][nt], ah0, bh.x, bh.y);    // Ah*Wh
                mma16816(d1[1][nt], ah1, bh.x, bh.y);
                mma16816(d1[0][nt], al0, bh.x, bh.y);    // Al*Wh
                mma16816(d1[1][nt], al1, bh.x, bh.y);
                mma16816(d1[0][nt], ah0, bl.x, bl.y);    // Ah*Wl
                mma16816(d1[1][nt], ah1, bl.x, bl.y);
            }
        }
        {   // kt3: K=48..55 only (K56-63 == 0) -> ldmatrix.x2 + k8 mma
            uint32_t ah0[2], ah1[2], al0[2], al1[2];
            ldm2(ah0, sAhi + rb0a + ((uint32_t)(6 ^ rrx0) << 4));
            ldm2(ah1, sAhi + rb1a + ((uint32_t)(6 ^ rrx1) << 4));
            ldm2(al0, sAlo + rb0a + ((uint32_t)(6 ^ rrx0) << 4));
            ldm2(al1, sAlo + rb1a + ((uint32_t)(6 ^ rrx1) << 4));
#pragma unroll
            for (int nt = 0; nt < 4; nt++) {
                uint32_t bh = W1H3[nt * 32 + lane];
                uint32_t bl = W1LO3[nt * 32 + lane];
                mma16808(d1[0][nt], ah0[0], ah0[1], bh);
                mma16808(d1[1][nt], ah1[0], ah1[1], bh);
                mma16808(d1[0][nt], al0[0], al0[1], bh);
                mma16808(d1[1][nt], al1[0], al1[1], bh);
                mma16808(d1[0][nt], ah0[0], ah0[1], bl);
                mma16808(d1[1][nt], ah1[0], ah1[1], bl);
            }
        }

        // ---- ReLU + hi/lo split -> layer-2 A fragments ----
        uint32_t a2h[2][2][4], a2l[2][2][4];
#pragma unroll
        for (int s = 0; s < 2; s++)
#pragma unroll
        for (int kt2 = 0; kt2 < 2; kt2++) {
#pragma unroll
            for (int hh = 0; hh < 2; hh++) {         // D1 n-tile = 2*kt2 + hh
                float* e = d1[s][2 * kt2 + hh];
                float r0 = fmaxf(e[0], 0.0f), r1 = fmaxf(e[1], 0.0f);
                float r2 = fmaxf(e[2], 0.0f), r3 = fmaxf(e[3], 0.0f);
                float t0 = bt(r0), t1 = bt(r1), t2 = bt(r2), t3 = bt(r3);
                a2h[s][kt2][hh * 2 + 0] = pk(t0, t1);
                a2h[s][kt2][hh * 2 + 1] = pk(t2, t3);
                a2l[s][kt2][hh * 2 + 0] = pk(r0 - t0, r1 - t1);
                a2l[s][kt2][hh * 2 + 1] = pk(r2 - t2, r3 - t3);
            }
        }

        // ---- layer 2: w2 bank fragments loaded once per tile ----
        float d2[2][2][4];
#pragma unroll
        for (int s = 0; s < 2; s++)
#pragma unroll
        for (int nt2 = 0; nt2 < 2; nt2++)
#pragma unroll
            for (int u = 0; u < 4; u++) d2[s][nt2][u] = 0.0f;

#pragma unroll
        for (int kt2 = 0; kt2 < 2; kt2++)
#pragma unroll
        for (int nt2 = 0; nt2 < 2; nt2++) {
            uint2 bh = W2H[(kt2 * 2 + nt2) * 32 + lane];
            uint2 bl = W2L[(kt2 * 2 + nt2) * 32 + lane];
#pragma unroll
            for (int s = 0; s < 2; s++) {
                mma16816(d2[s][nt2], a2h[s][kt2], bh.x, bh.y);
                mma16816(d2[s][nt2], a2h[s][kt2], bl.x, bl.y);
                mma16816(d2[s][nt2], a2l[s][kt2], bh.x, bh.y);
            }
        }

        // ---- stage z into the warp-private Alo overlay (pitch 17) ----
#pragma unroll
        for (int s = 0; s < 2; s++) {
            const int lr = s * 16 + nrow;
#pragma unroll
            for (int nt2 = 0; nt2 < 2; nt2++) {
                const int col = nt2 * 8 + q * 2;
                zsp[lr * 17 + col]           = d2[s][nt2][0];
                zsp[lr * 17 + col + 1]       = d2[s][nt2][1];
                zsp[(lr + 8) * 17 + col]     = d2[s][nt2][2];
                zsp[(lr + 8) * 17 + col + 1] = d2[s][nt2][3];
            }
        }
        __syncwarp();

        float z[13];
#pragma unroll
        for (int m = 0; m < 13; m++) z[m] = zsp[lane * 17 + m] + B2S[m];
        epilogue(z, dd, p, out);
        __syncwarp();   // overlay reads complete before next tile's Alo pack
    }
}

extern "C" void kernel_launch(void* const* d_in, const int* in_sizes, int n_in,
                              void* d_out, int out_size)
{
    const float* se  = (const float*)d_in[0];
    const float* te  = (const float*)d_in[1];
    const float* sr  = (const float*)d_in[2];
    const float* hc  = (const float*)d_in[3];
    const float* rot = (const float*)d_in[4];
    const float* w1  = (const float*)d_in[5];
    const float* b1  = (const float*)d_in[6];
    const float* w2  = (const float*)d_in[7];
    const float* b2  = (const float*)d_in[8];
    float* out = (float*)d_out;

    energy_cnn_hmma_kernel<<<NCTA, 128>>>(se, te, sr, hc, rot, w1, b1, w2, b2, out);
}